// round 16
// baseline (speedup 1.0000x reference)
#include <cuda_runtime.h>
#include <cuda_bf16.h>

// Problem constants (from reference)
#define GX 352
#define GY 400
#define GZ 1
#define BSZ 4
#define NSEG (BSZ * GZ * GY * GX)   // 563200
#define NPTS 2000000
#define CH 4

#define STHR 256
#define NB   ((NPTS + STHR - 1) / STHR)   // 7813 scatter CTAs
#define ZK   296                           // first-wave CTAs that zero the output
#define N4   ((NSEG * CH + NSEG) / 4)      // 704000 float4s of output

// Output layout: [ mean: NSEG*4 f32 ][ counts: NSEG f32 ]

// Zero-completion flag. 0 at replay start (finalize resets it), ZK when the
// output is fully zeroed. Values stay in [0, ZK] within a replay.
__device__ unsigned g_zero_done;

// ---- Phase 0+1 fused: first-wave zeroing + scatter ----
__global__ void __launch_bounds__(STHR)
scatter_kernel(const float4* __restrict__ feats,
               const int4* __restrict__ coors,
               float4* __restrict__ sums,
               float* __restrict__ counts) {
    const int bid = blockIdx.x;
    int i = bid * STHR + threadIdx.x;

    // Prefetch point data first (independent of the output buffer).
    int4  c;
    float4 f;
    bool valid = (i < NPTS);
    if (valid) {
        c = coors[i];
        f = feats[i];
    }

    float4* out4 = (float4*)sums;    // sums is the start of the output buffer

    if (bid < ZK) {
        // Worker CTA: zero a strided slice of the output, release the flag.
        const int stride = ZK * STHR;                 // 75776
        const float4 z = make_float4(0.f, 0.f, 0.f, 0.f);
        for (int j = bid * STHR + threadIdx.x; j < N4; j += stride)
            out4[j] = z;
        __threadfence();                              // release my zero stores
        __syncthreads();                              // whole CTA's stores fenced
        if (threadIdx.x == 0)
            atomicAdd(&g_zero_done, 1u);
    }

    // Gate: no RED may fire before the output is fully zeroed.
    if (threadIdx.x == 0) {
        while (*((volatile unsigned*)&g_zero_done) < ZK) { }
    }
    __syncthreads();
    __threadfence();                                  // acquire zero stores

    if (valid) {
        int seg = ((c.x * GZ + c.y) * GY + c.z) * GX + c.w;
        atomicAdd(&sums[seg], f);                     // RED.128 (fire-and-forget)
        atomicAdd(&counts[seg], 1.0f);                // RED.32
    }
    // NO fence/atomic after the REDs — keep them fire-and-forget (R15 lesson).
}

// ---- Phase 2: in-place mean = sums / max(count,1); reset the flag ----
__global__ void __launch_bounds__(256)
finalize_kernel(float4* __restrict__ sums,
                const float* __restrict__ counts) {
    int s = blockIdx.x * blockDim.x + threadIdx.x;
    cudaGridDependencySynchronize();                  // scatter grid fully done
    if (blockIdx.x == 0 && threadIdx.x == 0)
        g_zero_done = 0u;                             // arm next replay
    if (s >= NSEG) return;
    float cnt = counts[s];
    float inv = 1.0f / fmaxf(cnt, 1.0f);
    float4 v = sums[s];
    v.x *= inv; v.y *= inv; v.z *= inv; v.w *= inv;
    sums[s] = v;                                      // in-place: sums -> mean
}

static inline void launch_pdl(void* func, dim3 grid, dim3 block,
                              void** args, bool pdl) {
    cudaLaunchConfig_t cfg = {};
    cfg.gridDim = grid;
    cfg.blockDim = block;
    cfg.dynamicSmemBytes = 0;
    cfg.stream = 0;                                   // capture (legacy) stream
    cudaLaunchAttribute attr[1];
    if (pdl) {
        attr[0].id = cudaLaunchAttributeProgrammaticStreamSerialization;
        attr[0].val.programmaticStreamSerializationAllowed = 1;
        cfg.attrs = attr;
        cfg.numAttrs = 1;
    }
    cudaLaunchKernelExC(&cfg, func, args);
}

extern "C" void kernel_launch(void* const* d_in, const int* in_sizes, int n_in,
                              void* d_out, int out_size) {
    const float4* feats = (const float4*)d_in[0];     // (NPTS, 4) f32
    const int4*   coors = (const int4*)d_in[1];       // (NPTS, 4) i32
    float* out = (float*)d_out;

    float4* sums   = (float4*)out;                    // NSEG float4
    float*  counts = out + (size_t)NSEG * CH;         // NSEG floats

    // 1) fused zero + scatter (single node; zeroing done by first-wave CTAs)
    {
        void* args[] = { (void*)&feats, (void*)&coors, &sums, &counts };
        launch_pdl((void*)scatter_kernel, dim3(NB), dim3(STHR), args, false);
    }

    // 2) finalize (PDL: launch overlaps scatter tail) + flag reset
    {
        void* args[] = { &sums, &counts };
        int blocks = (NSEG + 255) / 256;
        launch_pdl((void*)finalize_kernel, dim3(blocks), dim3(256), args, true);
    }
}